// round 6
// baseline (speedup 1.0000x reference)
#include <cuda_runtime.h>

// ---------------------------------------------------------------------------
// pLoss via mma.sync (bf16 HMMA): pot = S f^T ; P = softmax_s ; pMargin = P^T S.
// No shift: S binary => |pot| <= ~26, exp(pot) in fp32 range; uniform per-row
// shifts don't change relative accuracy.
// f is an exact hi/lo bf16 split (pot exact up to fp32 accumulation).
// w is rn-rounded bf16; Z sums the SAME rounded values (errors cancel in M/Z).
// S pre-converted to bf16 once; main loop: 3-stage cp.async tile pipeline.
// Chunk body pipelined in two s-halves: GEMM1(h) -> exp(h) -> GEMM2 k-partial(h).
// 296 CTAs (74 splits x 4 batch-tiles) = 2 CTAs/SM, one wave.
// finalize does the final loss reduction via last-block pattern (3 launches).
// ---------------------------------------------------------------------------

#define NB       512
#define NL       64
#define SPLITS   74
#define CPS      7           // chunks per split (73*7 + 1 = 512)
#define TOTCH    512

#define SSOF(b)  ((b) * 9216)      // 3 tile buffers, 64 rows x 144B each
#define SMEM_BYTES 34816           // f staging (pre-loop) needs 128*272 = 34816

__device__ unsigned short g_Sbf[32768 * 64];   // bf16 copy of S (4 MB)
__device__ float g_Zpart[SPLITS * NB];
__device__ float g_Mpart[SPLITS * NB * NL];
__device__ float g_lpart[256];
__device__ unsigned g_cnt;                     // zero-init; self-resetting

// ---------------- helpers ----------------
__device__ __forceinline__ unsigned smem_u32(const void* p) {
    unsigned a;
    asm("{ .reg .u64 t; cvta.to.shared.u64 t, %1; cvt.u32.u64 %0, t; }"
        : "=r"(a) : "l"(p));
    return a;
}
__device__ __forceinline__ void ldsm4(unsigned* r, unsigned addr) {
    asm volatile("ldmatrix.sync.aligned.m8n8.x4.shared.b16 {%0,%1,%2,%3}, [%4];"
                 : "=r"(r[0]), "=r"(r[1]), "=r"(r[2]), "=r"(r[3]) : "r"(addr));
}
__device__ __forceinline__ void ldsm4t(unsigned* r, unsigned addr) {
    asm volatile("ldmatrix.sync.aligned.m8n8.x4.trans.shared.b16 {%0,%1,%2,%3}, [%4];"
                 : "=r"(r[0]), "=r"(r[1]), "=r"(r[2]), "=r"(r[3]) : "r"(addr));
}
__device__ __forceinline__ void mma16816(float* d, const unsigned* a,
                                         unsigned b0, unsigned b1) {
    asm volatile(
        "mma.sync.aligned.m16n8k16.row.col.f32.bf16.bf16.f32 "
        "{%0,%1,%2,%3}, {%4,%5,%6,%7}, {%8,%9}, {%0,%1,%2,%3};"
        : "+f"(d[0]), "+f"(d[1]), "+f"(d[2]), "+f"(d[3])
        : "r"(a[0]), "r"(a[1]), "r"(a[2]), "r"(a[3]), "r"(b0), "r"(b1));
}
__device__ __forceinline__ unsigned packhi(float a, float b) {   // exact trunc
    return __byte_perm(__float_as_uint(a), __float_as_uint(b), 0x7632);
}
__device__ __forceinline__ unsigned packlo(float a, float b) {   // exact residual
    float la = a - __uint_as_float(__float_as_uint(a) & 0xFFFF0000u);
    float lb = b - __uint_as_float(__float_as_uint(b) & 0xFFFF0000u);
    unsigned r;
    asm("cvt.rn.bf16x2.f32 %0, %1, %2;" : "=r"(r) : "f"(lb), "f"(la));
    return r;
}
__device__ __forceinline__ unsigned packrn(float a, float b) {   // rn round
    unsigned r;
    asm("cvt.rn.bf16x2.f32 %0, %1, %2;" : "=r"(r) : "f"(b), "f"(a));
    return r;
}
__device__ __forceinline__ void cpasync16(unsigned saddr, const void* g) {
    asm volatile("cp.async.cg.shared.global [%0], [%1], 16;"
                 :: "r"(saddr), "l"(g));
}
__device__ __forceinline__ void cp_commit() {
    asm volatile("cp.async.commit_group;" ::: "memory");
}
__device__ __forceinline__ void cp_wait1() {
    asm volatile("cp.async.wait_group 1;" ::: "memory");
}

// ---------------- S -> bf16 conversion ----------------
__global__ void conv_kernel(const float* __restrict__ S) {
    const int t = blockIdx.x * 256 + threadIdx.x;     // 8 elems each
    float4 a = ((const float4*)S)[2 * t];
    float4 b = ((const float4*)S)[2 * t + 1];
    uint4 o;
    o.x = packrn(a.x, a.y);  o.y = packrn(a.z, a.w);
    o.z = packrn(b.x, b.y);  o.w = packrn(b.z, b.w);
    ((uint4*)g_Sbf)[t] = o;
}

// ---------------- main kernel ----------------
__global__ __launch_bounds__(256, 2)
void main_kernel(const float* __restrict__ f) {
    extern __shared__ char smem[];
    const unsigned sb = smem_u32(smem);

    const int tid  = threadIdx.x;
    const int wid  = tid >> 5;
    const int lane = tid & 31;
    const int b0   = blockIdx.y * 128;
    const int c0   = blockIdx.x * CPS;
    const int c1   = min(c0 + CPS, TOTCH);

    // ---- stage f hi/lo split into SMEM ----
    {
        const int b = tid >> 1, half = tid & 1;
        const float* fr = f + (size_t)(b0 + b) * NL + half * 32;
        char* frow = smem + b * 272;
        #pragma unroll
        for (int j = 0; j < 8; j++) {
            float4 v = *(const float4*)(fr + 4 * j);
            int ch = half * 32 + 4 * j;
            *(uint2*)(frow + ch * 2) =
                make_uint2(packhi(v.x, v.y), packhi(v.z, v.w));
            *(uint2*)(frow + (64 + ch) * 2) =
                make_uint2(packlo(v.x, v.y), packlo(v.z, v.w));
        }
    }
    __syncthreads();

    // ---- A fragments (f hi: q=0..3, f lo: q=4..7), persistent ----
    unsigned fa[8][4];
    const int r0 = wid * 16;
    {
        const unsigned laneA = (lane % 16) * 272 + (lane >> 4) * 16;
        #pragma unroll
        for (int q = 0; q < 8; q++)
            ldsm4(fa[q], sb + r0 * 272 + q * 32 + laneA);
    }
    __syncthreads();   // staging dead; cp.async buffers may now be written

    // ---- cp.async pipeline prologue ----
    const int q0 = tid, q1 = tid + 256;
    const unsigned so0 = (unsigned)((q0 >> 3) * 144 + (q0 & 7) * 16);
    const unsigned so1 = (unsigned)((q1 >> 3) * 144 + (q1 & 7) * 16);

    #define ISSUE(c, buf)                                                   \
        do {                                                                \
            const char* gb_ = (const char*)g_Sbf + (size_t)(c) * 8192;      \
            cpasync16(sb + SSOF(buf) + so0, gb_ + q0 * 16);                 \
            cpasync16(sb + SSOF(buf) + so1, gb_ + q1 * 16);                 \
        } while (0)

    ISSUE(c0, 0); cp_commit();
    if (c0 + 1 < c1) ISSUE(c0 + 1, 1);
    cp_commit();

    // ---- chunk loop ----
    float macc[8][4];
    #pragma unroll
    for (int j = 0; j < 8; j++)
        #pragma unroll
        for (int k = 0; k < 4; k++) macc[j][k] = 0.f;
    float zacc0 = 0.f, zacc1 = 0.f;

    const unsigned laneB = (lane & 7) * 144 + (lane >> 3) * 16;  // GEMM1
    const unsigned laneT = lane * 144;                           // GEMM2 (trans)

    for (int c = c0; c < c1; c++) {
        const int idx = c - c0;
        const int buf = idx % 3;

        cp_wait1();
        __syncthreads();

        if (c + 2 < c1) ISSUE(c + 2, (idx + 2) % 3);
        cp_commit();

        const unsigned ssb = sb + SSOF(buf) + laneB;
        const unsigned sst = sb + SSOF(buf) + laneT;

        // two s-halves: GEMM1(h) -> exp(h) -> GEMM2 k-partial(h)
        #pragma unroll
        for (int h = 0; h < 2; h++) {
            // ---- GEMM1: scores[16 rows][32 s] for this half ----
            float d[4][4];
            #pragma unroll
            for (int j = 0; j < 4; j++)
                #pragma unroll
                for (int k = 0; k < 4; k++) d[j][k] = 0.f;

            #pragma unroll
            for (int j = 0; j < 4; j++) {
                #pragma unroll
                for (int qp = 0; qp < 2; qp++) {
                    unsigned bfr[4];
                    ldsm4(bfr, ssb + (h * 4 + j) * 1152 + qp * 64);
                    mma16816(d[j], fa[2 * qp],     bfr[0], bfr[1]);
                    mma16816(d[j], fa[2 * qp + 1], bfr[2], bfr[3]);
                    mma16816(d[j], fa[4 + 2 * qp],     bfr[0], bfr[1]);
                    mma16816(d[j], fa[4 + 2 * qp + 1], bfr[2], bfr[3]);
                }
            }

            // ---- epilogue: w = rn_bf16(exp(pot)); Z from rounded values ----
            unsigned wh[2][4];
            #pragma unroll
            for (int j = 0; j < 4; j++) {
                float e0 = __expf(d[j][0]);
                float e1 = __expf(d[j][1]);
                float e2 = __expf(d[j][2]);
                float e3 = __expf(d[j][3]);
                const int q = j >> 1, bx = (j & 1) * 2;
                unsigned p01 = packrn(e0, e1);
                unsigned p23 = packrn(e2, e3);
                wh[q][bx]     = p01;
                wh[q][bx + 1] = p23;
                zacc0 += __uint_as_float(p01 << 16) +
                         __uint_as_float(p01 & 0xFFFF0000u);
                zacc1 += __uint_as_float(p23 << 16) +
                         __uint_as_float(p23 & 0xFFFF0000u);
            }

            // ---- GEMM2 k-partial: M[16 rows][64 i] += w_h . S_h ----
            #pragma unroll
            for (int j = 0; j < 8; j++) {
                unsigned bfr[4];
                ldsm4t(bfr, sst + h * 4608 + j * 16);
                mma16816(macc[j], wh[0], bfr[0], bfr[1]);
                mma16816(macc[j], wh[1], bfr[2], bfr[3]);
            }
        }
    }
    #undef ISSUE

    // ---- Z partials (quad reduce) ----
    zacc0 += __shfl_xor_sync(0xFFFFFFFFu, zacc0, 1);
    zacc0 += __shfl_xor_sync(0xFFFFFFFFu, zacc0, 2);
    zacc1 += __shfl_xor_sync(0xFFFFFFFFu, zacc1, 1);
    zacc1 += __shfl_xor_sync(0xFFFFFFFFu, zacc1, 2);
    if ((lane & 3) == 0) {
        const int r = b0 + r0 + (lane >> 2);
        g_Zpart[blockIdx.x * NB + r]     = zacc0;
        g_Zpart[blockIdx.x * NB + r + 8] = zacc1;
    }

    // ---- M partials writeback ----
    {
        float* mb = g_Mpart + (size_t)blockIdx.x * (NB * NL)
                  + (size_t)(b0 + r0 + (lane >> 2)) * NL + (lane & 3) * 2;
        float* mb2 = mb + 8 * NL;
        #pragma unroll
        for (int j = 0; j < 8; j++) {
            *(float2*)(mb  + 8 * j) = make_float2(macc[j][0], macc[j][1]);
            *(float2*)(mb2 + 8 * j) = make_float2(macc[j][2], macc[j][3]);
        }
    }
}

// ------- finalize: splits sum, pMargin, BCE, last-block loss reduce -------
__global__ void finalize_kernel(const float* __restrict__ y,
                                const float* __restrict__ mask,
                                float* __restrict__ out) {
    const int half = threadIdx.x >> 7;
    const int el   = threadIdx.x & 127;
    const int idx  = blockIdx.x * 128 + el;

    float m = 0.f;
    const int kbase = half * 37;
    #pragma unroll
    for (int k = 0; k < 37; k++)
        m += g_Mpart[(size_t)(kbase + k) * (NB * NL) + idx];

    __shared__ float buf[128];
    __shared__ float red[256];
    __shared__ float Zsm[2];
    __shared__ int slast;
    if (threadIdx.x < 2) {
        float z = 0.f;
        #pragma unroll
        for (int k = 0; k < SPLITS; k++)
            z += g_Zpart[k * NB + blockIdx.x * 2 + threadIdx.x];
        Zsm[threadIdx.x] = z;
    }
    if (half) buf[el] = m;
    __syncthreads();

    float bce = 0.f;
    if (!half) {
        m += buf[el];
        float p = m / Zsm[el >> 6];
        out[1 + idx] = p;
        float yv = y[idx], mv = mask[idx];
        float lp  = fmaxf(logf(p), -100.f);
        float l1p = fmaxf(logf(fmaxf(1.f - p, 0.f)), -100.f);
        bce = -(yv * lp + (1.f - yv) * l1p) * mv;
    }
    red[threadIdx.x] = bce;
    __syncthreads();
    #pragma unroll
    for (int off = 128; off > 0; off >>= 1) {
        if (threadIdx.x < off) red[threadIdx.x] += red[threadIdx.x + off];
        __syncthreads();
    }

    // last-block final reduction (deterministic: fixed-order sum of 256 vals)
    if (threadIdx.x == 0) {
        g_lpart[blockIdx.x] = red[0];
        __threadfence();
        unsigned t = atomicAdd(&g_cnt, 1u);
        slast = (t == gridDim.x - 1) ? 1 : 0;
    }
    __syncthreads();
    if (slast) {
        red[threadIdx.x] = g_lpart[threadIdx.x];
        __syncthreads();
        #pragma unroll
        for (int off = 128; off > 0; off >>= 1) {
            if (threadIdx.x < off) red[threadIdx.x] += red[threadIdx.x + off];
            __syncthreads();
        }
        if (threadIdx.x == 0) {
            out[0] = red[0] * (1.f / NB);
            g_cnt = 0;                       // reset for next graph replay
        }
    }
}

extern "C" void kernel_launch(void* const* d_in, const int* in_sizes, int n_in,
                              void* d_out, int out_size) {
    const float* f    = (const float*)d_in[0];
    const float* S    = (const float*)d_in[1];
    const float* y    = (const float*)d_in[2];
    const float* mask = (const float*)d_in[3];
    float* out = (float*)d_out;

    conv_kernel<<<1024, 256>>>(S);
    dim3 grid(SPLITS, 4);
    main_kernel<<<grid, 256, SMEM_BYTES>>>(f);
    finalize_kernel<<<NB * NL / 128, 256>>>(y, mask, out);
}